// round 1
// baseline (speedup 1.0000x reference)
#include <cuda_runtime.h>
#include <cstddef>

#define EDIM 1024
#define BLK  256

// Scratch for the combined output vector y = W @ z + b (4 KB).
__device__ float g_y[EDIM];

// ---------------------------------------------------------------------------
// Kernel 1: compute z[e] for all wires, then one matvec row per block.
// grid = EDIM blocks (one per output feature f), BLK threads each.
// Each block recomputes z into shared memory (trivially cheap trig), then
// dots W[f, :] with z and reduces.
// ---------------------------------------------------------------------------
__global__ void __launch_bounds__(BLK)
compute_y_kernel(const float* __restrict__ bs_theta,
                 const float* __restrict__ bs_phi,
                 const float* __restrict__ phases,
                 const float* __restrict__ squeeze_r,
                 const float* __restrict__ disp_r,
                 const float* __restrict__ W,
                 const float* __restrict__ bvec) {
    __shared__ float zsh[EDIM];
    const int tid = threadIdx.x;
    const int f   = blockIdx.x;

    const float th0 = bs_theta[0];
    const float th1 = bs_phi[0];
    const float c0 = cosf(0.5f * th0), s0 = sinf(0.5f * th0);
    const float c1 = cosf(0.5f * th1), s1 = sinf(0.5f * th1);

    #pragma unroll
    for (int k = 0; k < EDIM / BLK; k++) {
        const int e = tid + BLK * k;

        // psi = (a, b) = ((1,0), (0,0)) complex
        float ar = 1.f, ai = 0.f, br = 0.f, bi = 0.f;

        // rx(bs_theta):  a' = c*a - i*s*b ; b' = -i*s*a + c*b
        {
            float nar =  c0 * ar + s0 * bi;
            float nai =  c0 * ai - s0 * br;
            float nbr =  s0 * ai + c0 * br;
            float nbi = -s0 * ar + c0 * bi;
            ar = nar; ai = nai; br = nbr; bi = nbi;
        }
        // ry(bs_phi):   a' = c*a - s*b ; b' = s*a + c*b
        {
            float nar = c1 * ar - s1 * br;
            float nai = c1 * ai - s1 * bi;
            float nbr = s1 * ar + c1 * br;
            float nbi = s1 * ai + c1 * bi;
            ar = nar; ai = nai; br = nbr; bi = nbi;
        }
        // rz(phases[e]): p = exp(-i*th/2) = (cp, -sp); a *= p; b *= conj(p)
        {
            float h = 0.5f * phases[e];
            float cp = cosf(h), sp = sinf(h);
            float nar = cp * ar + sp * ai;
            float nai = cp * ai - sp * ar;
            float nbr = cp * br - sp * bi;
            float nbi = cp * bi + sp * br;
            ar = nar; ai = nai; br = nbr; bi = nbi;
        }
        // ry(squeeze_r[e])
        {
            float h = 0.5f * squeeze_r[e];
            float c = cosf(h), s = sinf(h);
            float nar = c * ar - s * br;
            float nai = c * ai - s * bi;
            float nbr = s * ar + c * br;
            float nbi = s * ai + c * bi;
            ar = nar; ai = nai; br = nbr; bi = nbi;
        }
        // rx(displacement_r[e])
        {
            float h = 0.5f * disp_r[e];
            float c = cosf(h), s = sinf(h);
            float nar =  c * ar + s * bi;
            float nai =  c * ai - s * br;
            float nbr =  s * ai + c * br;
            float nbi = -s * ar + c * bi;
            ar = nar; ai = nai; br = nbr; bi = nbi;
        }
        // rz(kerr[e]) changes only phases -> |a|^2, |b|^2 unchanged. Skip it.

        zsh[e] = (ar * ar + ai * ai) - (br * br + bi * bi);
    }
    __syncthreads();

    // Dot W[f, :] with z.
    const float* __restrict__ wrow = W + (size_t)f * EDIM;
    float partial = 0.f;
    #pragma unroll
    for (int k = 0; k < EDIM / BLK; k++) {
        const int j = tid + BLK * k;
        partial += wrow[j] * zsh[j];
    }
    // warp reduce
    #pragma unroll
    for (int o = 16; o > 0; o >>= 1)
        partial += __shfl_down_sync(0xffffffffu, partial, o);

    __shared__ float red[BLK / 32];
    if ((tid & 31) == 0) red[tid >> 5] = partial;
    __syncthreads();
    if (tid < BLK / 32) {
        float s = red[tid];
        #pragma unroll
        for (int o = (BLK / 64); o > 0; o >>= 1)
            s += __shfl_down_sync(0xffu, s, o);
        if (tid == 0) g_y[f] = s + bvec[f];
    }
}

// ---------------------------------------------------------------------------
// Kernel 2: broadcast y over (B, S). Output layout (b, s, e): the fastest
// dim is exactly EDIM, and EDIM/4 == BLK, so with 256 threads per block and a
// grid stride that's a multiple of 256 float4s, every thread stores the SAME
// float4 = y4[threadIdx.x] forever. Hot loop = pure STG.128. DRAM-write-bound.
// ---------------------------------------------------------------------------
__global__ void __launch_bounds__(BLK)
broadcast_kernel(float4* __restrict__ out, size_t n4) {
    const int tid = threadIdx.x;
    const float4 v = *reinterpret_cast<const float4*>(&g_y[tid * 4]);
    const size_t stride = (size_t)gridDim.x * BLK;
    for (size_t i = (size_t)blockIdx.x * BLK + tid; i < n4; i += stride)
        out[i] = v;
}

// ---------------------------------------------------------------------------
// Inputs (metadata order):
//   0: x (B,S,E) f32        -- UNUSED (output is x-independent)
//   1: bs_theta (1,) f32
//   2: bs_phi   (1,) f32
//   3: phases   (E,) f32
//   4: squeeze_r(E,) f32
//   5: displacement_r (E,) f32
//   6: kerr     (E,) f32    -- UNUSED (rz does not change |amp|^2)
//   7: W_combine (E,E) f32
//   8: b_combine (E,) f32
// Output: (B,S,E) f32
// ---------------------------------------------------------------------------
extern "C" void kernel_launch(void* const* d_in, const int* in_sizes, int n_in,
                              void* d_out, int out_size) {
    const float* bs_theta = (const float*)d_in[1];
    const float* bs_phi   = (const float*)d_in[2];
    const float* phases   = (const float*)d_in[3];
    const float* squeeze  = (const float*)d_in[4];
    const float* disp     = (const float*)d_in[5];
    const float* W        = (const float*)d_in[7];
    const float* bvec     = (const float*)d_in[8];

    compute_y_kernel<<<EDIM, BLK>>>(bs_theta, bs_phi, phases, squeeze, disp,
                                    W, bvec);

    const size_t n4 = (size_t)out_size / 4;   // out_size = B*S*E = 67,108,864
    // 2048 blocks * 256 threads -> each thread does exactly 32 stores for the
    // nominal size; grid-stride loop keeps it correct for any size.
    broadcast_kernel<<<2048, BLK>>>((float4*)d_out, n4);
}

// round 2
// speedup vs baseline: 1.1149x; 1.1149x over previous
#include <cuda_runtime.h>
#include <cstddef>

#define EDIM 1024
#define BLK  256

__device__ float g_z[EDIM];   // Pauli-Z expectations per wire
__device__ float g_y[EDIM];   // y = W @ z + b

// ---------------------------------------------------------------------------
// Kernel A: compute z[e] for all 1024 wires. One block, 1024 threads,
// one wire per thread. Trig work done exactly once.
// ---------------------------------------------------------------------------
__global__ void __launch_bounds__(EDIM)
compute_z_kernel(const float* __restrict__ bs_theta,
                 const float* __restrict__ bs_phi,
                 const float* __restrict__ phases,
                 const float* __restrict__ squeeze_r,
                 const float* __restrict__ disp_r) {
    const int e = threadIdx.x;

    const float c0 = cosf(0.5f * bs_theta[0]), s0 = sinf(0.5f * bs_theta[0]);
    const float c1 = cosf(0.5f * bs_phi[0]),   s1 = sinf(0.5f * bs_phi[0]);

    // psi = (a, b) starting at (1, 0)
    float ar = 1.f, ai = 0.f, br = 0.f, bi = 0.f;

    // rx(bs_theta): a' = c*a - i*s*b ; b' = -i*s*a + c*b
    {
        float nar =  c0 * ar + s0 * bi;
        float nai =  c0 * ai - s0 * br;
        float nbr =  s0 * ai + c0 * br;
        float nbi = -s0 * ar + c0 * bi;
        ar = nar; ai = nai; br = nbr; bi = nbi;
    }
    // ry(bs_phi): a' = c*a - s*b ; b' = s*a + c*b
    {
        float nar = c1 * ar - s1 * br;
        float nai = c1 * ai - s1 * bi;
        float nbr = s1 * ar + c1 * br;
        float nbi = s1 * ai + c1 * bi;
        ar = nar; ai = nai; br = nbr; bi = nbi;
    }
    // rz(phases[e]): p = exp(-i th/2); a *= p; b *= conj(p)
    {
        float h = 0.5f * phases[e];
        float cp = cosf(h), sp = sinf(h);
        float nar = cp * ar + sp * ai;
        float nai = cp * ai - sp * ar;
        float nbr = cp * br - sp * bi;
        float nbi = cp * bi + sp * br;
        ar = nar; ai = nai; br = nbr; bi = nbi;
    }
    // ry(squeeze_r[e])
    {
        float h = 0.5f * squeeze_r[e];
        float c = cosf(h), s = sinf(h);
        float nar = c * ar - s * br;
        float nai = c * ai - s * bi;
        float nbr = s * ar + c * br;
        float nbi = s * ai + c * bi;
        ar = nar; ai = nai; br = nbr; bi = nbi;
    }
    // rx(displacement_r[e])
    {
        float h = 0.5f * disp_r[e];
        float c = cosf(h), s = sinf(h);
        float nar =  c * ar + s * bi;
        float nai =  c * ai - s * br;
        float nbr =  s * ai + c * br;
        float nbi = -s * ar + c * bi;
        ar = nar; ai = nai; br = nbr; bi = nbi;
    }
    // rz(kerr) only rotates phases -> |a|^2, |b|^2 unchanged. Dropped.

    g_z[e] = (ar * ar + ai * ai) - (br * br + bi * bi);
}

// ---------------------------------------------------------------------------
// Kernel B: matvec y[f] = W[f,:] . z + b[f]. One block per output feature.
// z is 4 KB, read from L2 by every block; W read is the 4 MB that matters.
// ---------------------------------------------------------------------------
__global__ void __launch_bounds__(BLK)
matvec_kernel(const float* __restrict__ W, const float* __restrict__ bvec) {
    const int tid = threadIdx.x;
    const int f   = blockIdx.x;

    const float4* __restrict__ wrow =
        reinterpret_cast<const float4*>(W + (size_t)f * EDIM);
    const float4* __restrict__ z4 = reinterpret_cast<const float4*>(g_z);

    float partial = 0.f;
    // EDIM/4 = 256 float4s == BLK: exactly one float4 per thread.
    {
        float4 w = wrow[tid];
        float4 z = z4[tid];
        partial = w.x * z.x + w.y * z.y + w.z * z.z + w.w * z.w;
    }
    #pragma unroll
    for (int o = 16; o > 0; o >>= 1)
        partial += __shfl_down_sync(0xffffffffu, partial, o);

    __shared__ float red[BLK / 32];
    if ((tid & 31) == 0) red[tid >> 5] = partial;
    __syncthreads();
    if (tid < BLK / 32) {
        float s = red[tid];
        #pragma unroll
        for (int o = (BLK / 64); o > 0; o >>= 1)
            s += __shfl_down_sync(0xffu, s, o);
        if (tid == 0) g_y[f] = s + bvec[f];
    }
}

// ---------------------------------------------------------------------------
// Kernel C: broadcast y over (B, S). EDIM/4 == BLK, so every thread stores
// the same float4 forever. Streaming stores (.cs) — data is never re-read.
// ---------------------------------------------------------------------------
__global__ void __launch_bounds__(BLK)
broadcast_kernel(float4* __restrict__ out, size_t n4) {
    const int tid = threadIdx.x;
    const float4 v = *reinterpret_cast<const float4*>(&g_y[tid * 4]);
    const size_t stride = (size_t)gridDim.x * BLK;
    size_t i = (size_t)blockIdx.x * BLK + tid;

    // Main unrolled loop: 4 independent streaming stores per iteration.
    for (; i + 3 * stride < n4; i += 4 * stride) {
        __stcs(out + i,              v);
        __stcs(out + i + stride,     v);
        __stcs(out + i + 2 * stride, v);
        __stcs(out + i + 3 * stride, v);
    }
    for (; i < n4; i += stride)
        __stcs(out + i, v);
}

// ---------------------------------------------------------------------------
// Inputs (metadata order):
//   0: x (B,S,E) f32        -- UNUSED (output is x-independent)
//   1: bs_theta (1,) f32
//   2: bs_phi   (1,) f32
//   3: phases   (E,) f32
//   4: squeeze_r(E,) f32
//   5: displacement_r (E,) f32
//   6: kerr     (E,) f32    -- UNUSED (rz does not change |amp|^2)
//   7: W_combine (E,E) f32
//   8: b_combine (E,) f32
// Output: (B,S,E) f32
// ---------------------------------------------------------------------------
extern "C" void kernel_launch(void* const* d_in, const int* in_sizes, int n_in,
                              void* d_out, int out_size) {
    const float* bs_theta = (const float*)d_in[1];
    const float* bs_phi   = (const float*)d_in[2];
    const float* phases   = (const float*)d_in[3];
    const float* squeeze  = (const float*)d_in[4];
    const float* disp     = (const float*)d_in[5];
    const float* W        = (const float*)d_in[7];
    const float* bvec     = (const float*)d_in[8];

    compute_z_kernel<<<1, EDIM>>>(bs_theta, bs_phi, phases, squeeze, disp);
    matvec_kernel<<<EDIM, BLK>>>(W, bvec);

    const size_t n4 = (size_t)out_size / 4;   // 16,777,216 float4s
    broadcast_kernel<<<2048, BLK>>>((float4*)d_out, n4);
}

// round 3
// speedup vs baseline: 1.1238x; 1.0080x over previous
#include <cuda_runtime.h>
#include <cstddef>

#define EDIM 1024
#define BLK  256

__device__ float g_y[EDIM];   // y = W @ z + b

// ---------------------------------------------------------------------------
// Fused kernel: each of 1024 blocks recomputes z[0..1023] into shared memory
// using fast trig intrinsics (cheap: ~24 MUFU ops/thread), then computes
// y[f] = W[f,:] . z + b[f] for its own row f. The 4 MB W read dominates.
// ---------------------------------------------------------------------------
__global__ void __launch_bounds__(BLK)
compute_y_kernel(const float* __restrict__ bs_theta,
                 const float* __restrict__ bs_phi,
                 const float* __restrict__ phases,
                 const float* __restrict__ squeeze_r,
                 const float* __restrict__ disp_r,
                 const float* __restrict__ W,
                 const float* __restrict__ bvec) {
    __shared__ float zsh[EDIM];
    const int tid = threadIdx.x;
    const int f   = blockIdx.x;

    float c0, s0, c1, s1;
    __sincosf(0.5f * bs_theta[0], &s0, &c0);
    __sincosf(0.5f * bs_phi[0],   &s1, &c1);

    #pragma unroll
    for (int k = 0; k < EDIM / BLK; k++) {
        const int e = tid + BLK * k;

        // psi = (a, b) starting at (1, 0) complex
        float ar = 1.f, ai = 0.f, br = 0.f, bi = 0.f;

        // rx(bs_theta): a' = c*a - i*s*b ; b' = -i*s*a + c*b
        {
            float nar =  c0 * ar + s0 * bi;
            float nai =  c0 * ai - s0 * br;
            float nbr =  s0 * ai + c0 * br;
            float nbi = -s0 * ar + c0 * bi;
            ar = nar; ai = nai; br = nbr; bi = nbi;
        }
        // ry(bs_phi): a' = c*a - s*b ; b' = s*a + c*b
        {
            float nar = c1 * ar - s1 * br;
            float nai = c1 * ai - s1 * bi;
            float nbr = s1 * ar + c1 * br;
            float nbi = s1 * ai + c1 * bi;
            ar = nar; ai = nai; br = nbr; bi = nbi;
        }
        // rz(phases[e]): p = exp(-i th/2); a *= p; b *= conj(p)
        {
            float cp, sp;
            __sincosf(0.5f * phases[e], &sp, &cp);
            float nar = cp * ar + sp * ai;
            float nai = cp * ai - sp * ar;
            float nbr = cp * br - sp * bi;
            float nbi = cp * bi + sp * br;
            ar = nar; ai = nai; br = nbr; bi = nbi;
        }
        // ry(squeeze_r[e])
        {
            float c, s;
            __sincosf(0.5f * squeeze_r[e], &s, &c);
            float nar = c * ar - s * br;
            float nai = c * ai - s * bi;
            float nbr = s * ar + c * br;
            float nbi = s * ai + c * bi;
            ar = nar; ai = nai; br = nbr; bi = nbi;
        }
        // rx(displacement_r[e])
        {
            float c, s;
            __sincosf(0.5f * disp_r[e], &s, &c);
            float nar =  c * ar + s * bi;
            float nai =  c * ai - s * br;
            float nbr =  s * ai + c * br;
            float nbi = -s * ar + c * bi;
            ar = nar; ai = nai; br = nbr; bi = nbi;
        }
        // rz(kerr) rotates phases only -> |a|^2, |b|^2 unchanged. Dropped.

        zsh[e] = (ar * ar + ai * ai) - (br * br + bi * bi);
    }
    __syncthreads();

    // Dot W[f, :] with z. EDIM/4 == BLK: one float4 per thread.
    const float4* __restrict__ wrow =
        reinterpret_cast<const float4*>(W + (size_t)f * EDIM);
    const float4* __restrict__ z4 = reinterpret_cast<const float4*>(zsh);

    float4 w = wrow[tid];
    float4 z = z4[tid];
    float partial = w.x * z.x + w.y * z.y + w.z * z.z + w.w * z.w;

    #pragma unroll
    for (int o = 16; o > 0; o >>= 1)
        partial += __shfl_down_sync(0xffffffffu, partial, o);

    __shared__ float red[BLK / 32];
    if ((tid & 31) == 0) red[tid >> 5] = partial;
    __syncthreads();
    if (tid < BLK / 32) {
        float s = red[tid];
        #pragma unroll
        for (int o = (BLK / 64); o > 0; o >>= 1)
            s += __shfl_down_sync(0xffu, s, o);
        if (tid == 0) g_y[f] = s + bvec[f];
    }
}

// ---------------------------------------------------------------------------
// Broadcast y over (B, S). EDIM/4 == BLK, so every thread stores the same
// float4 forever. Streaming stores (.cs); unroll x8 for deep store queue.
// Hot loop = pure STG.128. DRAM-write-bound.
// ---------------------------------------------------------------------------
__global__ void __launch_bounds__(BLK)
broadcast_kernel(float4* __restrict__ out, size_t n4) {
    const int tid = threadIdx.x;
    const float4 v = *reinterpret_cast<const float4*>(&g_y[tid * 4]);
    const size_t stride = (size_t)gridDim.x * BLK;
    size_t i = (size_t)blockIdx.x * BLK + tid;

    for (; i + 7 * stride < n4; i += 8 * stride) {
        __stcs(out + i,              v);
        __stcs(out + i + stride,     v);
        __stcs(out + i + 2 * stride, v);
        __stcs(out + i + 3 * stride, v);
        __stcs(out + i + 4 * stride, v);
        __stcs(out + i + 5 * stride, v);
        __stcs(out + i + 6 * stride, v);
        __stcs(out + i + 7 * stride, v);
    }
    for (; i < n4; i += stride)
        __stcs(out + i, v);
}

// ---------------------------------------------------------------------------
// Inputs (metadata order):
//   0: x (B,S,E) f32        -- UNUSED (output is x-independent)
//   1: bs_theta (1,) f32
//   2: bs_phi   (1,) f32
//   3: phases   (E,) f32
//   4: squeeze_r(E,) f32
//   5: displacement_r (E,) f32
//   6: kerr     (E,) f32    -- UNUSED (rz does not change |amp|^2)
//   7: W_combine (E,E) f32
//   8: b_combine (E,) f32
// Output: (B,S,E) f32
// ---------------------------------------------------------------------------
extern "C" void kernel_launch(void* const* d_in, const int* in_sizes, int n_in,
                              void* d_out, int out_size) {
    const float* bs_theta = (const float*)d_in[1];
    const float* bs_phi   = (const float*)d_in[2];
    const float* phases   = (const float*)d_in[3];
    const float* squeeze  = (const float*)d_in[4];
    const float* disp     = (const float*)d_in[5];
    const float* W        = (const float*)d_in[7];
    const float* bvec     = (const float*)d_in[8];

    compute_y_kernel<<<EDIM, BLK>>>(bs_theta, bs_phi, phases, squeeze, disp,
                                    W, bvec);

    const size_t n4 = (size_t)out_size / 4;   // 16,777,216 float4s
    broadcast_kernel<<<2048, BLK>>>((float4*)d_out, n4);
}

// round 4
// speedup vs baseline: 1.1291x; 1.0047x over previous
#include <cuda_runtime.h>
#include <cstddef>

#define EDIM 1024
#define BLK  256

__device__ float g_z[EDIM];   // Pauli-Z expectations per wire
__device__ float g_y[EDIM];   // y = W @ z + b

// ---------------------------------------------------------------------------
// Kernel A: compute z[e] for all 1024 wires, trig done exactly once.
// 1 block x 1024 threads, fast-math intrinsics (args are ~N(0,1)*0.5, deep
// inside the accurate range of sin/cos.approx).
// ---------------------------------------------------------------------------
__global__ void __launch_bounds__(EDIM)
compute_z_kernel(const float* __restrict__ bs_theta,
                 const float* __restrict__ bs_phi,
                 const float* __restrict__ phases,
                 const float* __restrict__ squeeze_r,
                 const float* __restrict__ disp_r) {
    const int e = threadIdx.x;

    float c0, s0, c1, s1;
    __sincosf(0.5f * bs_theta[0], &s0, &c0);
    __sincosf(0.5f * bs_phi[0],   &s1, &c1);

    // psi = (a, b) starting at (1, 0) complex
    float ar = 1.f, ai = 0.f, br = 0.f, bi = 0.f;

    // rx(bs_theta): a' = c*a - i*s*b ; b' = -i*s*a + c*b
    {
        float nar =  c0 * ar + s0 * bi;
        float nai =  c0 * ai - s0 * br;
        float nbr =  s0 * ai + c0 * br;
        float nbi = -s0 * ar + c0 * bi;
        ar = nar; ai = nai; br = nbr; bi = nbi;
    }
    // ry(bs_phi): a' = c*a - s*b ; b' = s*a + c*b
    {
        float nar = c1 * ar - s1 * br;
        float nai = c1 * ai - s1 * bi;
        float nbr = s1 * ar + c1 * br;
        float nbi = s1 * ai + c1 * bi;
        ar = nar; ai = nai; br = nbr; bi = nbi;
    }
    // rz(phases[e]): p = exp(-i th/2); a *= p; b *= conj(p)
    {
        float cp, sp;
        __sincosf(0.5f * phases[e], &sp, &cp);
        float nar = cp * ar + sp * ai;
        float nai = cp * ai - sp * ar;
        float nbr = cp * br - sp * bi;
        float nbi = cp * bi + sp * br;
        ar = nar; ai = nai; br = nbr; bi = nbi;
    }
    // ry(squeeze_r[e])
    {
        float c, s;
        __sincosf(0.5f * squeeze_r[e], &s, &c);
        float nar = c * ar - s * br;
        float nai = c * ai - s * bi;
        float nbr = s * ar + c * br;
        float nbi = s * ai + c * bi;
        ar = nar; ai = nai; br = nbr; bi = nbi;
    }
    // rx(displacement_r[e])
    {
        float c, s;
        __sincosf(0.5f * disp_r[e], &s, &c);
        float nar =  c * ar + s * bi;
        float nai =  c * ai - s * br;
        float nbr =  s * ai + c * br;
        float nbi = -s * ar + c * bi;
        ar = nar; ai = nai; br = nbr; bi = nbi;
    }
    // rz(kerr) rotates phases only -> |a|^2, |b|^2 unchanged. Dropped.

    g_z[e] = (ar * ar + ai * ai) - (br * br + bi * bi);
}

// ---------------------------------------------------------------------------
// Kernel B: matvec y[f] = W[f,:] . z + b[f]. One block per output feature;
// one float4 per thread. W (4 MB) comes from DRAM once; z (4 KB) from L2.
// ---------------------------------------------------------------------------
__global__ void __launch_bounds__(BLK)
matvec_kernel(const float* __restrict__ W, const float* __restrict__ bvec) {
    const int tid = threadIdx.x;
    const int f   = blockIdx.x;

    const float4* __restrict__ wrow =
        reinterpret_cast<const float4*>(W + (size_t)f * EDIM);
    const float4* __restrict__ z4 = reinterpret_cast<const float4*>(g_z);

    float4 w = wrow[tid];
    float4 z = z4[tid];
    float partial = w.x * z.x + w.y * z.y + w.z * z.z + w.w * z.w;

    #pragma unroll
    for (int o = 16; o > 0; o >>= 1)
        partial += __shfl_down_sync(0xffffffffu, partial, o);

    __shared__ float red[BLK / 32];
    if ((tid & 31) == 0) red[tid >> 5] = partial;
    __syncthreads();
    if (tid < BLK / 32) {
        float s = red[tid];
        #pragma unroll
        for (int o = (BLK / 64); o > 0; o >>= 1)
            s += __shfl_down_sync(0xffu, s, o);
        if (tid == 0) g_y[f] = s + bvec[f];
    }
}

// ---------------------------------------------------------------------------
// Kernel C: broadcast y over (B, S). EDIM/4 == BLK, so every thread stores
// the same float4 forever. Streaming stores (.cs); 2048 blocks -> exactly
// 32 stores/thread. Hot loop = pure STG.128, DRAM-write-bound.
// ---------------------------------------------------------------------------
__global__ void __launch_bounds__(BLK)
broadcast_kernel(float4* __restrict__ out, size_t n4) {
    const int tid = threadIdx.x;
    const float4 v = *reinterpret_cast<const float4*>(&g_y[tid * 4]);
    const size_t stride = (size_t)gridDim.x * BLK;
    size_t i = (size_t)blockIdx.x * BLK + tid;

    for (; i + 7 * stride < n4; i += 8 * stride) {
        __stcs(out + i,              v);
        __stcs(out + i + stride,     v);
        __stcs(out + i + 2 * stride, v);
        __stcs(out + i + 3 * stride, v);
        __stcs(out + i + 4 * stride, v);
        __stcs(out + i + 5 * stride, v);
        __stcs(out + i + 6 * stride, v);
        __stcs(out + i + 7 * stride, v);
    }
    for (; i < n4; i += stride)
        __stcs(out + i, v);
}

// ---------------------------------------------------------------------------
// Inputs (metadata order):
//   0: x (B,S,E) f32        -- UNUSED (output is x-independent)
//   1: bs_theta (1,) f32
//   2: bs_phi   (1,) f32
//   3: phases   (E,) f32
//   4: squeeze_r(E,) f32
//   5: displacement_r (E,) f32
//   6: kerr     (E,) f32    -- UNUSED (rz does not change |amp|^2)
//   7: W_combine (E,E) f32
//   8: b_combine (E,) f32
// Output: (B,S,E) f32
// ---------------------------------------------------------------------------
extern "C" void kernel_launch(void* const* d_in, const int* in_sizes, int n_in,
                              void* d_out, int out_size) {
    const float* bs_theta = (const float*)d_in[1];
    const float* bs_phi   = (const float*)d_in[2];
    const float* phases   = (const float*)d_in[3];
    const float* squeeze  = (const float*)d_in[4];
    const float* disp     = (const float*)d_in[5];
    const float* W        = (const float*)d_in[7];
    const float* bvec     = (const float*)d_in[8];

    compute_z_kernel<<<1, EDIM>>>(bs_theta, bs_phi, phases, squeeze, disp);
    matvec_kernel<<<EDIM, BLK>>>(W, bvec);

    const size_t n4 = (size_t)out_size / 4;   // 16,777,216 float4s
    broadcast_kernel<<<2048, BLK>>>((float4*)d_out, n4);
}

// round 5
// speedup vs baseline: 1.1399x; 1.0095x over previous
#include <cuda_runtime.h>
#include <cstddef>

#define EDIM 1024
#define BLK  256

__device__ float g_z[EDIM];   // Pauli-Z expectations per wire
__device__ float g_y[EDIM];   // y = W @ z + b

// ---------------------------------------------------------------------------
// Kernel A: compute z[e] for all 1024 wires, trig done exactly once.
// 1 block x 1024 threads, fast-math intrinsics (args ~N(0,1)*0.5, deep inside
// the accurate range of sin/cos.approx). Triggers PDL completion right after
// the g_z store so the dependent matvec can consume early.
// ---------------------------------------------------------------------------
__global__ void __launch_bounds__(EDIM)
compute_z_kernel(const float* __restrict__ bs_theta,
                 const float* __restrict__ bs_phi,
                 const float* __restrict__ phases,
                 const float* __restrict__ squeeze_r,
                 const float* __restrict__ disp_r) {
    const int e = threadIdx.x;

    float c0, s0, c1, s1;
    __sincosf(0.5f * bs_theta[0], &s0, &c0);
    __sincosf(0.5f * bs_phi[0],   &s1, &c1);

    // psi = (a, b) starting at (1, 0) complex
    float ar = 1.f, ai = 0.f, br = 0.f, bi = 0.f;

    // rx(bs_theta): a' = c*a - i*s*b ; b' = -i*s*a + c*b
    {
        float nar =  c0 * ar + s0 * bi;
        float nai =  c0 * ai - s0 * br;
        float nbr =  s0 * ai + c0 * br;
        float nbi = -s0 * ar + c0 * bi;
        ar = nar; ai = nai; br = nbr; bi = nbi;
    }
    // ry(bs_phi): a' = c*a - s*b ; b' = s*a + c*b
    {
        float nar = c1 * ar - s1 * br;
        float nai = c1 * ai - s1 * bi;
        float nbr = s1 * ar + c1 * br;
        float nbi = s1 * ai + c1 * bi;
        ar = nar; ai = nai; br = nbr; bi = nbi;
    }
    // rz(phases[e]): p = exp(-i th/2); a *= p; b *= conj(p)
    {
        float cp, sp;
        __sincosf(0.5f * phases[e], &sp, &cp);
        float nar = cp * ar + sp * ai;
        float nai = cp * ai - sp * ar;
        float nbr = cp * br - sp * bi;
        float nbi = cp * bi + sp * br;
        ar = nar; ai = nai; br = nbr; bi = nbi;
    }
    // ry(squeeze_r[e])
    {
        float c, s;
        __sincosf(0.5f * squeeze_r[e], &s, &c);
        float nar = c * ar - s * br;
        float nai = c * ai - s * bi;
        float nbr = s * ar + c * br;
        float nbi = s * ai + c * bi;
        ar = nar; ai = nai; br = nbr; bi = nbi;
    }
    // rx(displacement_r[e])
    {
        float c, s;
        __sincosf(0.5f * disp_r[e], &s, &c);
        float nar =  c * ar + s * bi;
        float nai =  c * ai - s * br;
        float nbr =  s * ai + c * br;
        float nbi = -s * ar + c * bi;
        ar = nar; ai = nai; br = nbr; bi = nbi;
    }
    // rz(kerr) rotates phases only -> |a|^2, |b|^2 unchanged. Dropped.

    g_z[e] = (ar * ar + ai * ai) - (br * br + bi * bi);

    cudaTriggerProgrammaticLaunchCompletion();
}

// ---------------------------------------------------------------------------
// Kernel B: matvec y[f] = W[f,:] . z + b[f]. One block per output feature;
// one float4 per thread. PDL-dependent on compute_z: it launches concurrently,
// issues its W (4 MB, DRAM) and bias loads FIRST, then waits for z.
// ---------------------------------------------------------------------------
__global__ void __launch_bounds__(BLK)
matvec_kernel(const float* __restrict__ W, const float* __restrict__ bvec) {
    const int tid = threadIdx.x;
    const int f   = blockIdx.x;

    const float4* __restrict__ wrow =
        reinterpret_cast<const float4*>(W + (size_t)f * EDIM);

    // Independent loads overlap with compute_z's execution.
    float4 w = wrow[tid];
    float  bias = bvec[f];

    // Wait for g_z to be valid.
    cudaGridDependencySynchronize();

    const float4* __restrict__ z4 = reinterpret_cast<const float4*>(g_z);
    float4 z = z4[tid];
    float partial = w.x * z.x + w.y * z.y + w.z * z.z + w.w * z.w;

    #pragma unroll
    for (int o = 16; o > 0; o >>= 1)
        partial += __shfl_down_sync(0xffffffffu, partial, o);

    __shared__ float red[BLK / 32];
    if ((tid & 31) == 0) red[tid >> 5] = partial;
    __syncthreads();
    if (tid < BLK / 32) {
        float s = red[tid];
        #pragma unroll
        for (int o = (BLK / 64); o > 0; o >>= 1)
            s += __shfl_down_sync(0xffu, s, o);
        if (tid == 0) g_y[f] = s + bias;
    }
    cudaTriggerProgrammaticLaunchCompletion();
}

// ---------------------------------------------------------------------------
// Kernel C: broadcast y over (B, S). PDL-dependent on matvec: 2048 blocks get
// scheduled and ramped while the prologue runs, then sync and stream. Every
// thread stores the same float4 (EDIM/4 == BLK). Streaming stores (.cs);
// exactly 32 stores/thread. Hot loop = pure STG.128, DRAM-write-bound.
// ---------------------------------------------------------------------------
__global__ void __launch_bounds__(BLK)
broadcast_kernel(float4* __restrict__ out, size_t n4) {
    const int tid = threadIdx.x;
    const size_t stride = (size_t)gridDim.x * BLK;
    size_t i = (size_t)blockIdx.x * BLK + tid;

    // Wait for g_y, then load the broadcast value.
    cudaGridDependencySynchronize();
    const float4 v = *reinterpret_cast<const float4*>(&g_y[tid * 4]);

    for (; i + 7 * stride < n4; i += 8 * stride) {
        __stcs(out + i,              v);
        __stcs(out + i + stride,     v);
        __stcs(out + i + 2 * stride, v);
        __stcs(out + i + 3 * stride, v);
        __stcs(out + i + 4 * stride, v);
        __stcs(out + i + 5 * stride, v);
        __stcs(out + i + 6 * stride, v);
        __stcs(out + i + 7 * stride, v);
    }
    for (; i < n4; i += stride)
        __stcs(out + i, v);
}

// ---------------------------------------------------------------------------
// Inputs (metadata order):
//   0: x (B,S,E) f32        -- UNUSED (output is x-independent)
//   1: bs_theta (1,) f32
//   2: bs_phi   (1,) f32
//   3: phases   (E,) f32
//   4: squeeze_r(E,) f32
//   5: displacement_r (E,) f32
//   6: kerr     (E,) f32    -- UNUSED (rz does not change |amp|^2)
//   7: W_combine (E,E) f32
//   8: b_combine (E,) f32
// Output: (B,S,E) f32
// ---------------------------------------------------------------------------
extern "C" void kernel_launch(void* const* d_in, const int* in_sizes, int n_in,
                              void* d_out, int out_size) {
    const float* bs_theta = (const float*)d_in[1];
    const float* bs_phi   = (const float*)d_in[2];
    const float* phases   = (const float*)d_in[3];
    const float* squeeze  = (const float*)d_in[4];
    const float* disp     = (const float*)d_in[5];
    const float* W        = (const float*)d_in[7];
    const float* bvec     = (const float*)d_in[8];

    // Node 1: plain launch.
    compute_z_kernel<<<1, EDIM>>>(bs_theta, bs_phi, phases, squeeze, disp);

    // Node 2: PDL launch — overlaps with compute_z.
    {
        cudaLaunchConfig_t cfg = {};
        cfg.gridDim  = dim3(EDIM);
        cfg.blockDim = dim3(BLK);
        cfg.stream   = 0;
        cudaLaunchAttribute attr[1];
        attr[0].id = cudaLaunchAttributeProgrammaticStreamSerialization;
        attr[0].val.programmaticStreamSerializationAllowed = 1;
        cfg.attrs = attr;
        cfg.numAttrs = 1;
        cudaLaunchKernelEx(&cfg, matvec_kernel, W, bvec);
    }

    // Node 3: PDL launch — ramps up while prologue runs.
    const size_t n4 = (size_t)out_size / 4;   // 16,777,216 float4s
    {
        cudaLaunchConfig_t cfg = {};
        cfg.gridDim  = dim3(2048);
        cfg.blockDim = dim3(BLK);
        cfg.stream   = 0;
        cudaLaunchAttribute attr[1];
        attr[0].id = cudaLaunchAttributeProgrammaticStreamSerialization;
        attr[0].val.programmaticStreamSerializationAllowed = 1;
        cfg.attrs = attr;
        cfg.numAttrs = 1;
        cudaLaunchKernelEx(&cfg, broadcast_kernel, (float4*)d_out, n4);
    }
}